// round 1
// baseline (speedup 1.0000x reference)
#include <cuda_runtime.h>

// HoG layer, fused:
//   input  x: (1, 3, 4096, 4096) f32
//   output feat: (511, 511, 36) f32
// Only pixels (8cy+7, 8cx+7) are sampled, so we gather 4 neighbors of the
// channel-sum per cell, soft-bin into 9-bin hists in SMEM (tile + halo),
// then normalize 2x2-cell blocks and write 36 floats per block.

#define IMG   4096
#define CELLS 512
#define OUTD  511
#define TC    16          // cells per tile side
#define HW    (TC + 1)    // 17: tile + halo
#define NCELL (HW * HW)   // 289

__global__ __launch_bounds__(256)
void hog_fused_kernel(const float* __restrict__ x, float* __restrict__ out)
{
    __shared__ float hist[NCELL * 9];   // 2601 floats = 10404 B

    const int cx0 = blockIdx.x * TC;
    const int cy0 = blockIdx.y * TC;
    const int tid = threadIdx.x;
    const long chs = (long)IMG * IMG;   // channel stride

    // ---- Phase 1: per-cell histogram into SMEM (tile + halo) ----
    for (int c = tid; c < NCELL; c += 256) {
        const int lcy = c / HW;
        const int lcx = c - lcy * HW;
        const int cy = cy0 + lcy;
        const int cx = cx0 + lcx;

        float* hrow = &hist[c * 9];
        #pragma unroll
        for (int b = 0; b < 9; b++) hrow[b] = 0.0f;

        if (cy < CELLS && cx < CELLS) {
            const int py = cy * 8 + 7;
            const int px = cx * 8 + 7;
            const float* p = x + (long)py * IMG + px;

            float su = 0.f, sd = 0.f, sl = 0.f, sr = 0.f;
            const bool has_d = (py + 1 < IMG);   // false only for cy == 511
            const bool has_r = (px + 1 < IMG);   // false only for cx == 511
            #pragma unroll
            for (int ch = 0; ch < 3; ch++) {
                const float* pc = p + ch * chs;
                su += pc[-IMG];
                sl += pc[-1];
                if (has_d) sd += pc[IMG];
                if (has_r) sr += pc[1];
            }

            const float gv = sd - su;
            const float gh = sr - sl;
            const float mag = sqrtf(gv * gv + gh * gh + 1e-6f);
            const float ang = fabsf(atanf(gh / (gv + 1e-9f)))
                              * (180.0f / 3.14159265358979323846f);

            // j = floor(ang/20 - 0.5), ang in [0, 90] -> j in [-1, 4]
            const float t  = ang * 0.05f;                // ang / DELTA
            const int   ji = (int)floorf(t - 0.5f);
            const float vj  = mag * ((float)ji + 1.5f - t);
            const float vj1 = mag - vj;

            const int i0 = (ji < 0) ? 8 : ji;   // mod(ji, 9)
            const int i1 = ji + 1;              // in [0, 5], never == i0
            hrow[i0] = vj;
            hrow[i1] = vj1;
        }
    }
    __syncthreads();

    // ---- Phase 2: one output block per thread ----
    const int ly = tid >> 4;          // tid / 16
    const int lx = tid & 15;          // tid % 16
    const int oy = cy0 + ly;
    const int ox = cx0 + lx;
    if (oy >= OUTD || ox >= OUTD) return;

    const float* h00 = &hist[(ly * HW + lx) * 9];
    const float* h01 = h00 + 9;
    const float* h10 = h00 + HW * 9;
    const float* h11 = h10 + 9;

    float blk[36];
    #pragma unroll
    for (int b = 0; b < 9; b++) {
        blk[b]      = h00[b];
        blk[9  + b] = h01[b];
        blk[18 + b] = h10[b];
        blk[27 + b] = h11[b];
    }

    float ss = 0.f;
    #pragma unroll
    for (int b = 0; b < 36; b++) ss += blk[b] * blk[b];
    const float inv = 1.0f / (sqrtf(ss) + 1e-9f);

    // 36 floats = 144 B, 16B-aligned -> 9x STG.128
    float4* o4 = reinterpret_cast<float4*>(out + ((size_t)oy * OUTD + ox) * 36);
    #pragma unroll
    for (int b = 0; b < 9; b++) {
        o4[b] = make_float4(blk[4 * b + 0] * inv,
                            blk[4 * b + 1] * inv,
                            blk[4 * b + 2] * inv,
                            blk[4 * b + 3] * inv);
    }
}

extern "C" void kernel_launch(void* const* d_in, const int* in_sizes, int n_in,
                              void* d_out, int out_size)
{
    const float* x = (const float*)d_in[0];
    float* out = (float*)d_out;
    dim3 grid(CELLS / TC, CELLS / TC);   // 32 x 32 tiles
    hog_fused_kernel<<<grid, 256>>>(x, out);
}